// round 1
// baseline (speedup 1.0000x reference)
#include <cuda_runtime.h>
#include <cuda_bf16.h>

#define BB 512
#define LL 512
#define NN 128
#define GG 4   // batches per block

// Scratch (device globals — no allocation allowed)
__device__ float g_E[NN * NN];      // exp(trans)
__device__ float g_norm[BB];        // per-batch normalizer
__device__ float g_path[BB];        // per-batch path score

__device__ __forceinline__ unsigned long long ffma2(unsigned long long a,
                                                    unsigned long long b,
                                                    unsigned long long c) {
    unsigned long long d;
    asm("fma.rn.f32x2 %0, %1, %2, %3;" : "=l"(d) : "l"(a), "l"(b), "l"(c));
    return d;
}

__device__ __forceinline__ unsigned long long dup2(float e) {
    unsigned int u = __float_as_uint(e);
    return ((unsigned long long)u << 32) | (unsigned long long)u;
}

// ---------------------------------------------------------------------------
// Kernel 0: E = exp(trans)
// ---------------------------------------------------------------------------
__global__ void crf_expE(const float* __restrict__ trans) {
    int idx = blockIdx.x * blockDim.x + threadIdx.x;
    if (idx < NN * NN) g_E[idx] = __expf(trans[idx]);
}

// ---------------------------------------------------------------------------
// Kernel 1: forward recurrence (normalizer). 128 blocks x 512 threads.
// Block owns 4 batches. Thread tid = q*128 + j  (q in 0..3, j in 0..127).
//   Phase A (warps 0-3): per-batch max + p = exp(s - m)   (warp w -> batch w)
//   Phase B (all):       partial dot products, E in registers, f32x2 FMA
//   Phase C (all):       combine partials, log, add emission, update scores
// ---------------------------------------------------------------------------
__global__ __launch_bounds__(512, 1)
void crf_forward(const float* __restrict__ em,
                 const float* __restrict__ mask,
                 const float* __restrict__ start) {
    __shared__ float       sc[GG][NN];        // scores per batch
    __shared__ ulonglong2  p2s[NN];           // p[i] for 4 batches (float4 aliased)
    __shared__ float       part[4][GG][NN];   // partial sums [h][g][j]
    __shared__ float       msh[GG];           // per-batch max

    const int tid = threadIdx.x;
    const int q   = tid >> 7;     // 0..3 : i-range (phase B) / batch (phase C)
    const int j   = tid & 127;
    const int bbase = blockIdx.x * GG;

    // ---- Load E columns into registers (duplicated-lane packed pairs) ----
    unsigned long long E2[32];
#pragma unroll
    for (int ii = 0; ii < 32; ii++) {
        E2[ii] = dup2(g_E[(q * 32 + ii) * NN + j]);
    }

    // ---- Init scores: s0[j] = start[j] + em[b,0,j] ----
    const size_t embase = (size_t)(bbase + q) * LL * NN;
    sc[q][j] = start[j] + em[embase + j];

    // ---- Prefetch t=1 emission / mask ----
    float em_r = em[embase + NN + j];
    float mk_r = mask[(bbase + q) * LL + 1];
    __syncthreads();

    for (int t = 1; t < LL; t++) {
        // ---------------- Phase A: max + exp (warps 0-3) ----------------
        if (tid < 128) {
            const int g = tid >> 5, lane = tid & 31;
            float s0 = sc[g][lane];
            float s1 = sc[g][lane + 32];
            float s2 = sc[g][lane + 64];
            float s3 = sc[g][lane + 96];
            float mx = fmaxf(fmaxf(s0, s1), fmaxf(s2, s3));
#pragma unroll
            for (int o = 16; o; o >>= 1)
                mx = fmaxf(mx, __shfl_xor_sync(0xffffffffu, mx, o));
            float* pf = (float*)p2s;
            pf[lane * 4 + g]        = __expf(s0 - mx);
            pf[(lane + 32) * 4 + g] = __expf(s1 - mx);
            pf[(lane + 64) * 4 + g] = __expf(s2 - mx);
            pf[(lane + 96) * 4 + g] = __expf(s3 - mx);
            if (lane == 0) msh[g] = mx;
        }
        __syncthreads();

        // ---------------- Phase B: partial dots (all threads) -----------
        unsigned long long a01 = 0ull, a23 = 0ull;   // packed {0.f,0.f}
#pragma unroll
        for (int ii = 0; ii < 32; ii++) {
            ulonglong2 pv = p2s[q * 32 + ii];        // broadcast within warp
            a01 = ffma2(pv.x, E2[ii], a01);
            a23 = ffma2(pv.y, E2[ii], a23);
        }
        part[q][0][j] = __uint_as_float((unsigned int)a01);
        part[q][1][j] = __uint_as_float((unsigned int)(a01 >> 32));
        part[q][2][j] = __uint_as_float((unsigned int)a23);
        part[q][3][j] = __uint_as_float((unsigned int)(a23 >> 32));
        __syncthreads();

        // ---------------- Phase C: combine + update ---------------------
        float tot = part[0][q][j] + part[1][q][j] + part[2][q][j] + part[3][q][j];
        float snew = msh[q] + __logf(tot) + em_r;
        float sold = sc[q][j];
        snew = mk_r * snew + (1.0f - mk_r) * sold;

        // Prefetch next step
        if (t + 1 < LL) {
            em_r = em[embase + (size_t)(t + 1) * NN + j];
            mk_r = mask[(bbase + q) * LL + t + 1];
        }

        sc[q][j] = snew;
        __syncthreads();
    }

    // ---- Final per-batch logsumexp over states ----
    if (tid < 128) {
        const int g = tid >> 5, lane = tid & 31;
        float s0 = sc[g][lane];
        float s1 = sc[g][lane + 32];
        float s2 = sc[g][lane + 64];
        float s3 = sc[g][lane + 96];
        float mx = fmaxf(fmaxf(s0, s1), fmaxf(s2, s3));
#pragma unroll
        for (int o = 16; o; o >>= 1)
            mx = fmaxf(mx, __shfl_xor_sync(0xffffffffu, mx, o));
        float sum = __expf(s0 - mx) + __expf(s1 - mx) +
                    __expf(s2 - mx) + __expf(s3 - mx);
#pragma unroll
        for (int o = 16; o; o >>= 1)
            sum += __shfl_xor_sync(0xffffffffu, sum, o);
        if (lane == 0) g_norm[bbase + g] = mx + __logf(sum);
    }
}

// ---------------------------------------------------------------------------
// Kernel 2: path score. One block (128 threads) per batch.
// ---------------------------------------------------------------------------
__global__ __launch_bounds__(128)
void crf_path(const float* __restrict__ em,
              const int*   __restrict__ tgt,
              const float* __restrict__ mask,
              const float* __restrict__ start,
              const float* __restrict__ trans) {
    const int b = blockIdx.x;
    const int tid = threadIdx.x;
    __shared__ float red[128];

    const size_t embase = (size_t)b * LL * NN;
    float s = 0.0f;
    for (int t = tid; t < LL; t += 128) {
        if (t == 0) {
            int t0 = tgt[b * LL];
            s += start[t0] + em[embase + t0];
        } else {
            int prev = tgt[b * LL + t - 1];
            int cur  = tgt[b * LL + t];
            s += mask[b * LL + t] *
                 (trans[prev * NN + cur] + em[embase + (size_t)t * NN + cur]);
        }
    }
    red[tid] = s;
    __syncthreads();
#pragma unroll
    for (int o = 64; o; o >>= 1) {
        if (tid < o) red[tid] += red[tid + o];
        __syncthreads();
    }
    if (tid == 0) g_path[b] = red[0];
}

// ---------------------------------------------------------------------------
// Kernel 3: mean(normalizer - path)
// ---------------------------------------------------------------------------
__global__ __launch_bounds__(512)
void crf_final(float* __restrict__ out) {
    const int tid = threadIdx.x;
    __shared__ float red[512];
    red[tid] = g_norm[tid] - g_path[tid];
    __syncthreads();
#pragma unroll
    for (int o = 256; o; o >>= 1) {
        if (tid < o) red[tid] += red[tid + o];
        __syncthreads();
    }
    if (tid == 0) out[0] = red[0] * (1.0f / (float)BB);
}

// ---------------------------------------------------------------------------
// Launch
// ---------------------------------------------------------------------------
extern "C" void kernel_launch(void* const* d_in, const int* in_sizes, int n_in,
                              void* d_out, int out_size) {
    const float* emission    = (const float*)d_in[0];
    const int*   target      = (const int*)  d_in[1];
    const float* mask        = (const float*)d_in[2];
    const float* start_trans = (const float*)d_in[3];
    const float* trans       = (const float*)d_in[4];
    float* out = (float*)d_out;

    crf_expE<<<NN, NN>>>(trans);
    crf_forward<<<BB / GG, 512>>>(emission, mask, start_trans);
    crf_path<<<BB, 128>>>(emission, target, mask, start_trans, trans);
    crf_final<<<1, 512>>>(out);
}